// round 4
// baseline (speedup 1.0000x reference)
#include <cuda_runtime.h>
#include <cstdint>

#define B_   32
#define N_   64
#define GS_  80
#define NG_  6400
#define NA_  3
#define TK_  3
#define NC_  80

// output layout (floats), reference return order: bboxes, scores, anc, fg
#define BB_OFF  0
#define SC_OFF  (B_*NA_*NG_*4)                 // 2,457,600
#define ANC_OFF (SC_OFF + B_*NA_*NG_*NC_)      // 51,609,600
#define FG_OFF  (ANC_OFF + 6)                  // 51,609,606

// scratch (device globals — no allocation allowed)
__device__ int g_top3[B_ * N_ * TK_];
__device__ int g_asgn[B_ * NG_];   // packed: tgt(8) | label<<8 | fg<<16

typedef unsigned long long ull;

// ---------------- Kernel A: top-3 nearest cells per (b, gt) -----------------
// One THREAD per GT; candidates provably lie in the 7x7 window around the GT
// center (3rd-best L1 dist <= 2.0 incl. borders). key=(distbits<<32)|g min-
// select reproduces top_k's lowest-index tie-break exactly.
__global__ void topk_kernel(const float* __restrict__ gt_cxys) {
    const int bn = blockIdx.x * blockDim.x + threadIdx.x;
    if (bn >= B_ * N_) return;
    const float cx = gt_cxys[bn * 2 + 0];
    const float cy = gt_cxys[bn * 2 + 1];

    int xs = (int)floorf(cx) - 3; xs = xs < 0 ? 0 : (xs > GS_ - 7 ? GS_ - 7 : xs);
    int ys = (int)floorf(cy) - 3; ys = ys < 0 ? 0 : (ys > GS_ - 7 ? GS_ - 7 : ys);

    ull k0 = ~0ull, k1 = ~0ull, k2 = ~0ull;
#pragma unroll
    for (int dy = 0; dy < 7; dy++) {
        const int y = ys + dy;
        const float ady = fabsf(((float)y + 0.5f) - cy);
#pragma unroll
        for (int dx = 0; dx < 7; dx++) {
            const int x = xs + dx;
            const float d = fabsf(((float)x + 0.5f) - cx) + ady;
            const ull key = ((ull)__float_as_uint(d) << 32) | (unsigned)(y * GS_ + x);
            if (key < k2) {
                if (key < k0)      { k2 = k1; k1 = k0; k0 = key; }
                else if (key < k1) { k2 = k1; k1 = key; }
                else               { k2 = key; }
            }
        }
    }
    g_top3[bn * TK_ + 0] = (int)(k0 & 0xffffffffu);
    g_top3[bn * TK_ + 1] = (int)(k1 & 0xffffffffu);
    g_top3[bn * TK_ + 2] = (int)(k2 & 0xffffffffu);
}

// ------------- Kernel B: scatter claims, resolve -> tgt/label/fg -------------
__global__ void assign_kernel(const float* __restrict__ gt_cxys,
                              const float* __restrict__ mask_gt,
                              const int*   __restrict__ gt_labels) {
    const int b   = blockIdx.x;
    const int tid = threadIdx.x;   // blockDim = 256

    __shared__ int   claims[NG_];            // (count<<16) + sum_of_t
    __shared__ float scx[N_], scy[N_];
    __shared__ int   st[N_ * TK_];
    __shared__ int   slab[N_];

    for (int g = tid; g < NG_; g += 256) claims[g] = 0;
    if (tid < N_) {
        scx[tid]  = gt_cxys[(b * N_ + tid) * 2 + 0];
        scy[tid]  = gt_cxys[(b * N_ + tid) * 2 + 1];
        slab[tid] = gt_labels[b * N_ + tid];
    }
    if (tid < N_ * TK_) st[tid] = g_top3[b * N_ * TK_ + tid];
    __syncthreads();

    if (tid < N_ * TK_) {
        const int t = tid / TK_;
        const int g = st[tid];
        const float v = mask_gt[((size_t)(b * N_ + t)) * NG_ + g];
        if (v != 0.0f) atomicAdd(&claims[g], (1 << 16) + t);
    }
    __syncthreads();

    for (int g = tid; g < NG_; g += 256) {
        const int c   = claims[g];
        const int cnt = c >> 16;
        int tgt, fg;
        if (cnt == 0)      { tgt = 0;           fg = 0; }
        else if (cnt == 1) { tgt = c & 0xffff;  fg = 1; }
        else {
            // conflict: nearest GT over ALL 64 (ties -> lowest t); keep only
            // if that GT itself claims g (topk) AND is valid
            const float fx = (float)(g % GS_) + 0.5f;
            const float fy = (float)(g / GS_) + 0.5f;
            ull best = ~0ull;
            for (int t = 0; t < N_; t++) {
                const float d = fabsf(fx - scx[t]) + fabsf(fy - scy[t]);
                const ull key = ((ull)__float_as_uint(d) << 32) | (unsigned)t;
                best = key < best ? key : best;
            }
            const int mgt = (int)(best & 0xffffffffu);
            const bool mem = (st[mgt*3] == g) | (st[mgt*3+1] == g) | (st[mgt*3+2] == g);
            const bool has = mem && (mask_gt[((size_t)(b * N_ + mgt)) * NG_ + g] != 0.0f);
            fg  = has ? 1 : 0;
            tgt = has ? mgt : 0;
        }
        g_asgn[b * NG_ + g] = tgt | (slab[tgt] << 8) | (fg << 16);
    }
}

// ------------- Kernel C: bboxes (float4), fg mask, anc copy -------------
// grid (25, 96): blockIdx.y = b*NA+a, all index math 32-bit.
__global__ void box_kernel(const float* __restrict__ anc_wh,
                           const float* __restrict__ grid,
                           const float* __restrict__ gt_cxys,
                           const float* __restrict__ gt_whs,
                           float* __restrict__ out) {
    const int g  = blockIdx.x * blockDim.x + threadIdx.x;   // < NG_
    const int ba = blockIdx.y;                              // b*NA + a
    const int b  = ba / NA_;
    const int a  = ba - b * NA_;
    const int idx = ba * NG_ + g;

    const int packed = g_asgn[b * NG_ + g];
    const int tgt = packed & 0xff;
    const int fg  = (packed >> 16) & 1;

    const float cx = gt_cxys[(b * N_ + tgt) * 2 + 0];
    const float cy = gt_cxys[(b * N_ + tgt) * 2 + 1];
    const float w  = gt_whs [(b * N_ + tgt) * 2 + 0];
    const float h  = gt_whs [(b * N_ + tgt) * 2 + 1];
    const float gx = grid[g * 2 + 0];
    const float gy = grid[g * 2 + 1];

    reinterpret_cast<float4*>(out + BB_OFF)[idx] = make_float4(cx - gx, cy - gy, w, h);

    const float aw = anc_wh[a * 2 + 0], ah = anc_wh[a * 2 + 1];
    const float r1 = w / aw, r2 = h / ah;
    const float m  = fmaxf(fmaxf(r1, 1.0f / r1), fmaxf(r2, 1.0f / r2));
    out[FG_OFF + idx] = (fg && (m < 4.0f)) ? 1.0f : 0.0f;

    if (ba == 0 && g < 6) out[ANC_OFF + g] = anc_wh[g];
}

// ------------- Kernel D: one-hot scores -------------
// grid (125, 96): blockIdx.y = (b,a) slab of NG_*NC_ floats = 128000 float4.
// Each thread writes 4 float4s block-strided (coalesced); 32-bit const-divisor
// index math only.
#define SC_U 4
__global__ void score_kernel(float* __restrict__ out) {
    const int ba  = blockIdx.y;            // 0..95
    const int b   = ba / NA_;
    const int* __restrict__ asg = g_asgn + b * NG_;
    float4* __restrict__ dst =
        reinterpret_cast<float4*>(out + SC_OFF) + (size_t)ba * (NG_ * (NC_ / 4));

    int i = blockIdx.x * (256 * SC_U) + threadIdx.x;   // float4 idx in slab
#pragma unroll
    for (int u = 0; u < SC_U; u++, i += 256) {
        const int g  = i / (NC_ / 4);                  // const div: mulhi
        const int c  = (i - g * (NC_ / 4)) * 4;
        const int lab = (asg[g] >> 8) & 0xff;
        float4 v;
        v.x = (c + 0 == lab) ? 1.0f : 0.0f;
        v.y = (c + 1 == lab) ? 1.0f : 0.0f;
        v.z = (c + 2 == lab) ? 1.0f : 0.0f;
        v.w = (c + 3 == lab) ? 1.0f : 0.0f;
        dst[i] = v;
    }
}

extern "C" void kernel_launch(void* const* d_in, const int* in_sizes, int n_in,
                              void* d_out, int out_size) {
    const float* anc_wh    = (const float*)d_in[0];
    const float* grid      = (const float*)d_in[1];
    const int*   gt_labels = (const int*)  d_in[2];
    const float* gt_cxys   = (const float*)d_in[3];
    const float* gt_whs    = (const float*)d_in[4];
    const float* mask_gt   = (const float*)d_in[5];
    float* out = (float*)d_out;

    topk_kernel<<<(B_ * N_ + 255) / 256, 256>>>(gt_cxys);
    assign_kernel<<<B_, 256>>>(gt_cxys, mask_gt, gt_labels);

    dim3 gbox(NG_ / 256, B_ * NA_);
    box_kernel<<<gbox, 256>>>(anc_wh, grid, gt_cxys, gt_whs, out);

    dim3 gsc(NG_ * (NC_ / 4) / (256 * SC_U), B_ * NA_);   // (125, 96)
    score_kernel<<<gsc, 256>>>(out);
}